// round 12
// baseline (speedup 1.0000x reference)
#include <cuda_runtime.h>
#include <cuda_fp16.h>

#define NN 10000
#define NE 4000
#define MAXM (4 * 1024 * 1024)
#define PAD 64      // 256B stride between atomic counters -> spreads across all LTS slices
#define G 444       // persistent grid: 3 blocks/SM on 148 SMs, capacity 4/SM (launch_bounds)

// scan chunk layout: 256 counters per chunk
#define SC_E 32     // ceil(2*NE / 256)
#define SC_N 40     // ceil(NN / 256)
#define SC_T (SC_E + SC_N)  // 72 scanning blocks

// ---------------- device scratch (zero-initialized at module load) ----------------
__device__ float g_VT[128 * 128];
__device__ float g_cc[128];
__device__ __half g_Y[NN * 128];
__device__ __half g_emean[2 * NE * 64];
__device__ int g_ecnt[2 * NE * PAD];   // zeroed by scan after reading (invariant)
__device__ int g_epos[2 * NE * PAD];
__device__ int g_eptr[2 * NE + 1];
__device__ int g_n1cnt[NN * PAD];      // zeroed by scan after reading (invariant)
__device__ int g_n1pos[NN * PAD];
__device__ int g_n1ptr[NN + 1];
__device__ int g_n2ptr[NN + 1];        // fully rewritten each call
__device__ int g_emem[MAXM];
__device__ int g_nmem1[MAXM];
__device__ int g_bsumE[SC_E];          // overwritten before read each call
__device__ int g_bsumN[SC_N];
__device__ volatile int g_bar[4];      // per-site monotonic ticket counters

// grid-wide barrier: separate counter per site; volatile-load polling (no RMW spin)
__device__ __forceinline__ void grid_barrier(int idx) {
    __syncthreads();
    if (threadIdx.x == 0) {
        __threadfence();
        int ticket = atomicAdd((int*)&g_bar[idx], 1);
        int target = ticket - (ticket % G) + G;
        while (g_bar[idx] < target) {}
        __threadfence();
    }
    __syncthreads();
}

// ---------------- side-stream plumbing ----------------
struct HxPlumbing {
    cudaStream_t side;
    cudaEvent_t ev_fork, ev_gemm;
    HxPlumbing() {
        cudaStreamCreateWithFlags(&side, cudaStreamNonBlocking);
        cudaEventCreateWithFlags(&ev_fork, cudaEventDisableTiming);
        cudaEventCreateWithFlags(&ev_gemm, cudaEventDisableTiming);
    }
};
static HxPlumbing hx;

// ---------------- fold weights (side stream) ----------------
__global__ void fold_kernel(const float* __restrict__ W1, const float* __restrict__ b1,
                            const float* __restrict__ W2, const float* __restrict__ b2,
                            const float* __restrict__ Wout) {
    int bb = blockIdx.x;
    if (bb < 64) {
        int idx = bb * 256 + threadIdx.x;
        int j = idx >> 7, k = idx & 127;
        int s = j >> 6, jo = j & 63;
        const float* W = s ? W2 : W1;
        float sum = 0.f;
#pragma unroll 8
        for (int h = 0; h < 128; h++) sum = fmaf(Wout[jo * 128 + h], W[h * 128 + k], sum);
        g_VT[k * 128 + j] = sum;
    } else {
        int j = threadIdx.x;
        if (j < 128) {
            int s = j >> 6, jo = j & 63;
            const float* b = s ? b2 : b1;
            float sum = 0.f;
#pragma unroll 8
            for (int h = 0; h < 128; h++) sum = fmaf(Wout[jo * 128 + h], b[h], sum);
            g_cc[j] = sum;
        }
    }
}

// ---------------- GEMM (side stream): Y = x @ Vcat^T + cc, fp16 out ----------------
#define GEMM_BLOCKS ((NN + 31) / 32)  // 313

#define FMA4(a, sc, v)                 \
    a.x = fmaf(sc, v.x, a.x);          \
    a.y = fmaf(sc, v.y, a.y);          \
    a.z = fmaf(sc, v.z, a.z);          \
    a.w = fmaf(sc, v.w, a.w);

__global__ __launch_bounds__(256) void gemm_kernel(const float* __restrict__ x) {
    int tx = threadIdx.x & 31;
    int ty = threadIdx.x >> 5;
    int row0 = blockIdx.x * 32 + ty * 4;
    const float4* x4 = (const float4*)x;
    const float4* v4 = (const float4*)g_VT;

    int rb0 = (row0 + 0 < NN ? row0 + 0 : NN - 1) * 32;
    int rb1 = (row0 + 1 < NN ? row0 + 1 : NN - 1) * 32;
    int rb2 = (row0 + 2 < NN ? row0 + 2 : NN - 1) * 32;
    int rb3 = (row0 + 3 < NN ? row0 + 3 : NN - 1) * 32;

    float4 a0 = make_float4(0.f, 0.f, 0.f, 0.f), a1 = a0, a2 = a0, a3 = a0;

#pragma unroll 4
    for (int k4 = 0; k4 < 32; k4++) {
        float4 v0 = v4[(4 * k4 + 0) * 32 + tx];
        float4 v1 = v4[(4 * k4 + 1) * 32 + tx];
        float4 v2 = v4[(4 * k4 + 2) * 32 + tx];
        float4 v3 = v4[(4 * k4 + 3) * 32 + tx];
        float4 q;
        q = x4[rb0 + k4];
        FMA4(a0, q.x, v0); FMA4(a0, q.y, v1); FMA4(a0, q.z, v2); FMA4(a0, q.w, v3);
        q = x4[rb1 + k4];
        FMA4(a1, q.x, v0); FMA4(a1, q.y, v1); FMA4(a1, q.z, v2); FMA4(a1, q.w, v3);
        q = x4[rb2 + k4];
        FMA4(a2, q.x, v0); FMA4(a2, q.y, v1); FMA4(a2, q.z, v2); FMA4(a2, q.w, v3);
        q = x4[rb3 + k4];
        FMA4(a3, q.x, v0); FMA4(a3, q.y, v1); FMA4(a3, q.z, v2); FMA4(a3, q.w, v3);
    }
    float4 c = ((const float4*)g_cc)[tx];
    a0.x += c.x; a0.y += c.y; a0.z += c.z; a0.w += c.w;
    a1.x += c.x; a1.y += c.y; a1.z += c.z; a1.w += c.w;
    a2.x += c.x; a2.y += c.y; a2.z += c.z; a2.w += c.w;
    a3.x += c.x; a3.y += c.y; a3.z += c.z; a3.w += c.w;

    union { __half2 h[2]; uint2 u; } cv;
#define STORE_ROW(rr, aa)                                             \
    if (row0 + rr < NN) {                                             \
        cv.h[0] = __floats2half2_rn(aa.x, aa.y);                      \
        cv.h[1] = __floats2half2_rn(aa.z, aa.w);                      \
        ((uint2*)g_Y)[(row0 + rr) * 32 + tx] = cv.u;                  \
    }
    STORE_ROW(0, a0) STORE_ROW(1, a1) STORE_ROW(2, a2) STORE_ROW(3, a3)
#undef STORE_ROW
}

// ---------------- build kernel: hist -> scan -> fill with grid barriers ----------------
__global__ __launch_bounds__(256, 4) void build_kernel(const int* __restrict__ hi1,
                                                       const int* __restrict__ hi2,
                                                       int nnz1, int nnz2) {
    const int T = G * 256;
    int gid = blockIdx.x * 256 + threadIdx.x;
    int t = threadIdx.x, lane = t & 31, wid = t >> 5;

    // ---- Phase H: histogram + n2 run boundaries + tail ----
    if (nnz2 > 0) {
        int last = __ldg(&hi2[nnz2 - 1]);
        for (int k = gid; k < NN - last; k += T) g_n2ptr[last + 1 + k] = nnz2;
        for (int i = gid * 8; i < nnz2; i += T * 8) {
            int lim = (i + 8 <= nnz2) ? 8 : (nnz2 - i);
            int e[8], nd[8];
#pragma unroll
            for (int u = 0; u < 8; u++) {
                if (u < lim) {
                    e[u] = __ldg(&hi2[nnz2 + i + u]);
                    nd[u] = __ldg(&hi2[i + u]);
                }
            }
#pragma unroll
            for (int u = 0; u < 8; u++) {
                if (u < lim) atomicAdd(&g_ecnt[(NE + e[u]) * PAD], 1);
            }
            int pv = (i == 0) ? -1 : __ldg(&hi2[i - 1]);
#pragma unroll
            for (int u = 0; u < 8; u++) {
                if (u < lim) {
                    if (nd[u] != pv) {
                        for (int n = pv + 1; n <= nd[u]; n++) g_n2ptr[n] = i + u;
                    }
                    pv = nd[u];
                }
            }
        }
    }
    for (int k = gid; k < nnz1; k += T) {
        int node = __ldg(&hi1[k]), edge = __ldg(&hi1[nnz1 + k]);
        atomicAdd(&g_ecnt[edge * PAD], 1);
        atomicAdd(&g_n1cnt[node * PAD], 1);
    }

    grid_barrier(0);

    // ---- Phase S: scan (blocks 0..SC_T-1 only; others just hit barriers) ----
    __shared__ int wsum[8];
    __shared__ int s_off;
    int b = blockIdx.x;
    bool scanner = (b < SC_T);
    int excl = 0, v = 0, i_sc = 0, n_sc = 0, lb = 0, nb = 0;
    int *ptr = 0, *pos = 0;

    if (scanner) {
        int* cnt;
        int* bsum;
        bool isE = (b < SC_E);
        if (isE) { cnt = g_ecnt; ptr = g_eptr; pos = g_epos; n_sc = 2 * NE; lb = b; nb = SC_E; bsum = g_bsumE; }
        else { cnt = g_n1cnt; ptr = g_n1ptr; pos = g_n1pos; n_sc = NN; lb = b - SC_E; nb = SC_N; bsum = g_bsumN; }
        i_sc = lb * 256 + t;

        v = (i_sc < n_sc) ? cnt[i_sc * PAD] : 0;
        if (i_sc < n_sc) cnt[i_sc * PAD] = 0;  // re-zero (call-entry invariant)

        int inc = v;
#pragma unroll
        for (int o = 1; o < 32; o <<= 1) {
            int u = __shfl_up_sync(~0u, inc, o);
            if (lane >= o) inc += u;
        }
        if (lane == 31) wsum[wid] = inc;
        __syncthreads();
        if (wid == 0 && lane < 8) {
            int w = wsum[lane];
            int wi = w;
#pragma unroll
            for (int o = 1; o < 8; o <<= 1) {
                int u = __shfl_up_sync(0xffu, wi, o);
                if (lane >= o) wi += u;
            }
            wsum[lane] = wi - w;
        }
        __syncthreads();
        excl = wsum[wid] + inc - v;
        if (t == 255) bsum[lb] = excl + v;
    }

    grid_barrier(1);

    if (scanner) {
        const int* bsum = (b < SC_E) ? g_bsumE : g_bsumN;
        if (wid == 0) {
            int acc = 0;
            for (int q = lane; q < lb; q += 32) acc += bsum[q];
#pragma unroll
            for (int o = 16; o > 0; o >>= 1) acc += __shfl_down_sync(~0u, acc, o);
            if (lane == 0) s_off = acc;
        }
        __syncthreads();
        int off = s_off;
        if (i_sc < n_sc) { ptr[i_sc] = excl + off; pos[i_sc * PAD] = excl + off; }
        if (lb == nb - 1 && t == 255) ptr[n_sc] = off + excl + v;
    }

    grid_barrier(2);

    // ---- Phase F: fill CSR ----
    for (int i = gid * 8; i < nnz2; i += T * 8) {
        int lim = (i + 8 <= nnz2) ? 8 : (nnz2 - i);
        if (lim == 8) {
            int nd[8], e[8], p[8];
#pragma unroll
            for (int u = 0; u < 8; u++) {
                nd[u] = __ldg(&hi2[i + u]);
                e[u] = __ldg(&hi2[nnz2 + i + u]);
            }
#pragma unroll
            for (int u = 0; u < 8; u++) p[u] = atomicAdd(&g_epos[(NE + e[u]) * PAD], 1);
#pragma unroll
            for (int u = 0; u < 8; u++) g_emem[p[u]] = nd[u];
        } else {
            for (int u = i; u < nnz2; u++) {
                int n0 = __ldg(&hi2[u]), e0 = __ldg(&hi2[nnz2 + u]);
                int p = atomicAdd(&g_epos[(NE + e0) * PAD], 1);
                g_emem[p] = n0;
            }
        }
    }
    for (int k = gid; k < nnz1; k += T) {
        int node = __ldg(&hi1[k]), edge = __ldg(&hi1[nnz1 + k]);
        int p = atomicAdd(&g_epos[edge * PAD], 1);
        int q = atomicAdd(&g_n1pos[node * PAD], 1);
        g_emem[p] = node;
        g_nmem1[q] = edge;
    }
}

// ---------------- gather kernel: edge_mean -> barrier -> node_out ----------------
__global__ __launch_bounds__(256, 4) void gather_kernel(const int* __restrict__ hi2, int nnz2,
                                                        const float* __restrict__ bout,
                                                        float* __restrict__ out) {
    int lane = threadIdx.x & 31;
    int wg = (blockIdx.x * 256 + threadIdx.x) >> 5;
    const int NW = G * 8;

    // ---- Phase E: per-edge-slot mean ----
    const __half2* Y2 = (const __half2*)g_Y;
    for (int w = wg; w < 2 * NE; w += NW) {
        int beg = g_eptr[w], end = g_eptr[w + 1];
        int col = ((w >= NE) ? 32 : 0) + lane;
        float sx = 0.f, sy = 0.f;
        int j = beg;
        for (; j + 8 <= end; j += 8) {
            float2 f[8];
#pragma unroll
            for (int u = 0; u < 8; u++) {
                int n0 = g_emem[j + u];
                f[u] = __half22float2(Y2[n0 * 64 + col]);
            }
#pragma unroll
            for (int u = 0; u < 8; u++) { sx += f[u].x; sy += f[u].y; }
        }
        for (; j < end; j++) {
            int n0 = g_emem[j];
            float2 a = __half22float2(Y2[n0 * 64 + col]);
            sx += a.x;
            sy += a.y;
        }
        int cnt = end - beg;
        float inv = 1.f / (float)(cnt > 0 ? cnt : 1);
        ((__half2*)g_emean)[w * 32 + lane] = __floats2half2_rn(sx * inv, sy * inv);
    }

    grid_barrier(3);

    // ---- Phase N: per-node output ----
    const __half2* E2 = (const __half2*)g_emean;
    const int* hi2e = hi2 + nnz2;
    for (int w = wg; w < NN; w += NW) {
        float sx = 0.f, sy = 0.f;
        {
            int beg = g_n1ptr[w], end = g_n1ptr[w + 1];
            int j = beg;
            for (; j + 4 <= end; j += 4) {
                float2 f[4];
#pragma unroll
                for (int u = 0; u < 4; u++) {
                    int e = g_nmem1[j + u];
                    f[u] = __half22float2(E2[e * 32 + lane]);
                }
#pragma unroll
                for (int u = 0; u < 4; u++) { sx += f[u].x; sy += f[u].y; }
            }
            for (; j < end; j++) {
                int e = g_nmem1[j];
                float2 a = __half22float2(E2[e * 32 + lane]);
                sx += a.x;
                sy += a.y;
            }
        }
        {
            int beg = g_n2ptr[w], end = g_n2ptr[w + 1];
            int j = beg;
            for (; j + 8 <= end; j += 8) {
                float2 f[8];
#pragma unroll
                for (int u = 0; u < 8; u++) {
                    int e = __ldg(&hi2e[j + u]);
                    f[u] = __half22float2(E2[(NE + e) * 32 + lane]);
                }
#pragma unroll
                for (int u = 0; u < 8; u++) { sx += f[u].x; sy += f[u].y; }
            }
            for (; j < end; j++) {
                int e = __ldg(&hi2e[j]);
                float2 a = __half22float2(E2[(NE + e) * 32 + lane]);
                sx += a.x;
                sy += a.y;
            }
        }
        float2 bo = ((const float2*)bout)[lane];
        ((float2*)out)[w * 32 + lane] = make_float2(bo.x + 0.5f * sx, bo.y + 0.5f * sy);
    }
}

// ---------------- launcher: forked-stream DAG, 2 kernels on critical path ----------------
extern "C" void kernel_launch(void* const* d_in, const int* in_sizes, int n_in,
                              void* d_out, int out_size) {
    const float* x = (const float*)d_in[0];
    const int* hi1 = (const int*)d_in[1];
    const int* hi2 = (const int*)d_in[2];
    const float* W1 = (const float*)d_in[3];
    const float* b1 = (const float*)d_in[4];
    const float* W2 = (const float*)d_in[5];
    const float* b2 = (const float*)d_in[6];
    const float* Wout = (const float*)d_in[7];
    const float* bout = (const float*)d_in[8];
    float* out = (float*)d_out;

    int nnz1 = in_sizes[1] / 2;
    int nnz2 = in_sizes[2] / 2;

    // Fork: side branch computes fold -> gemm
    cudaEventRecord(hx.ev_fork, 0);
    cudaStreamWaitEvent(hx.side, hx.ev_fork, 0);
    fold_kernel<<<65, 256, 0, hx.side>>>(W1, b1, W2, b2, Wout);
    gemm_kernel<<<GEMM_BLOCKS, 256, 0, hx.side>>>(x);
    cudaEventRecord(hx.ev_gemm, hx.side);

    // Main branch: CSR build (hist+scan+fill fused via grid barriers)
    build_kernel<<<G, 256>>>(hi1, hi2, nnz1, nnz2);

    // Join, then fused gather (edge_mean + node_out)
    cudaStreamWaitEvent(0, hx.ev_gemm, 0);
    gather_kernel<<<G, 256>>>(hi2, nnz2, bout, out);
}

// round 13
// speedup vs baseline: 1.0611x; 1.0611x over previous
#include <cuda_runtime.h>
#include <cuda_fp16.h>

#define NN 10000
#define NE 4000
#define MAXM (4 * 1024 * 1024)
#define PAD 64      // 256B stride between atomic counters -> spreads across all LTS slices
#define G 444       // persistent grid: 3 blocks/SM x 148 SMs, guaranteed by launch_bounds(512,3)
#define BT 512      // threads per block

// scan chunk layout: 512 counters per chunk
#define SC_E 16     // ceil(2*NE / 512)
#define SC_N 20     // ceil(NN / 512)
#define SC_T (SC_E + SC_N)

// ---------------- device scratch (zero-initialized at module load) ----------------
__device__ float g_VT[128 * 128];
__device__ float g_cc[128];
__device__ __half g_Y[NN * 128];
__device__ __half g_emean[2 * NE * 64];
__device__ int g_ecnt[2 * NE * PAD];   // zeroed by scan after reading (invariant)
__device__ int g_epos[2 * NE * PAD];
__device__ int g_eptr[2 * NE + 1];
__device__ int g_n1cnt[NN * PAD];      // zeroed by scan after reading (invariant)
__device__ int g_n1pos[NN * PAD];
__device__ int g_n1ptr[NN + 1];
__device__ int g_n2ptr[NN + 1];        // fully rewritten each call
__device__ int g_emem[MAXM];
__device__ int g_nmem1[MAXM];
__device__ int g_bsumE[SC_E];          // overwritten before read each call
__device__ int g_bsumN[SC_N];
__device__ volatile int g_bar[4];      // per-site monotonic ticket counters

// grid-wide barrier: per-site counter; volatile-load polling
__device__ __forceinline__ void grid_barrier(int idx) {
    __syncthreads();
    if (threadIdx.x == 0) {
        __threadfence();
        int ticket = atomicAdd((int*)&g_bar[idx], 1);
        int target = ticket - (ticket % G) + G;
        while (g_bar[idx] < target) {}
        __threadfence();
    }
    __syncthreads();
}

// ---------------- side-stream plumbing ----------------
struct HxPlumbing {
    cudaStream_t side;
    cudaEvent_t ev_fork, ev_gemm;
    HxPlumbing() {
        cudaStreamCreateWithFlags(&side, cudaStreamNonBlocking);
        cudaEventCreateWithFlags(&ev_fork, cudaEventDisableTiming);
        cudaEventCreateWithFlags(&ev_gemm, cudaEventDisableTiming);
    }
};
static HxPlumbing hx;

// ---------------- fold weights (side stream) ----------------
__global__ void fold_kernel(const float* __restrict__ W1, const float* __restrict__ b1,
                            const float* __restrict__ W2, const float* __restrict__ b2,
                            const float* __restrict__ Wout) {
    int bb = blockIdx.x;
    if (bb < 64) {
        int idx = bb * 256 + threadIdx.x;
        int j = idx >> 7, k = idx & 127;
        int s = j >> 6, jo = j & 63;
        const float* W = s ? W2 : W1;
        float sum = 0.f;
#pragma unroll 8
        for (int h = 0; h < 128; h++) sum = fmaf(Wout[jo * 128 + h], W[h * 128 + k], sum);
        g_VT[k * 128 + j] = sum;
    } else {
        int j = threadIdx.x;
        if (j < 128) {
            int s = j >> 6, jo = j & 63;
            const float* b = s ? b2 : b1;
            float sum = 0.f;
#pragma unroll 8
            for (int h = 0; h < 128; h++) sum = fmaf(Wout[jo * 128 + h], b[h], sum);
            g_cc[j] = sum;
        }
    }
}

// ---------------- GEMM (side stream): Y = x @ Vcat^T + cc, fp16 out ----------------
#define GEMM_BLOCKS ((NN + 31) / 32)  // 313

#define FMA4(a, sc, v)                 \
    a.x = fmaf(sc, v.x, a.x);          \
    a.y = fmaf(sc, v.y, a.y);          \
    a.z = fmaf(sc, v.z, a.z);          \
    a.w = fmaf(sc, v.w, a.w);

__global__ __launch_bounds__(256) void gemm_kernel(const float* __restrict__ x) {
    int tx = threadIdx.x & 31;
    int ty = threadIdx.x >> 5;
    int row0 = blockIdx.x * 32 + ty * 4;
    const float4* x4 = (const float4*)x;
    const float4* v4 = (const float4*)g_VT;

    int rb0 = (row0 + 0 < NN ? row0 + 0 : NN - 1) * 32;
    int rb1 = (row0 + 1 < NN ? row0 + 1 : NN - 1) * 32;
    int rb2 = (row0 + 2 < NN ? row0 + 2 : NN - 1) * 32;
    int rb3 = (row0 + 3 < NN ? row0 + 3 : NN - 1) * 32;

    float4 a0 = make_float4(0.f, 0.f, 0.f, 0.f), a1 = a0, a2 = a0, a3 = a0;

#pragma unroll 4
    for (int k4 = 0; k4 < 32; k4++) {
        float4 v0 = v4[(4 * k4 + 0) * 32 + tx];
        float4 v1 = v4[(4 * k4 + 1) * 32 + tx];
        float4 v2 = v4[(4 * k4 + 2) * 32 + tx];
        float4 v3 = v4[(4 * k4 + 3) * 32 + tx];
        float4 q;
        q = x4[rb0 + k4];
        FMA4(a0, q.x, v0); FMA4(a0, q.y, v1); FMA4(a0, q.z, v2); FMA4(a0, q.w, v3);
        q = x4[rb1 + k4];
        FMA4(a1, q.x, v0); FMA4(a1, q.y, v1); FMA4(a1, q.z, v2); FMA4(a1, q.w, v3);
        q = x4[rb2 + k4];
        FMA4(a2, q.x, v0); FMA4(a2, q.y, v1); FMA4(a2, q.z, v2); FMA4(a2, q.w, v3);
        q = x4[rb3 + k4];
        FMA4(a3, q.x, v0); FMA4(a3, q.y, v1); FMA4(a3, q.z, v2); FMA4(a3, q.w, v3);
    }
    float4 c = ((const float4*)g_cc)[tx];
    a0.x += c.x; a0.y += c.y; a0.z += c.z; a0.w += c.w;
    a1.x += c.x; a1.y += c.y; a1.z += c.z; a1.w += c.w;
    a2.x += c.x; a2.y += c.y; a2.z += c.z; a2.w += c.w;
    a3.x += c.x; a3.y += c.y; a3.z += c.z; a3.w += c.w;

    union { __half2 h[2]; uint2 u; } cv;
#define STORE_ROW(rr, aa)                                             \
    if (row0 + rr < NN) {                                             \
        cv.h[0] = __floats2half2_rn(aa.x, aa.y);                      \
        cv.h[1] = __floats2half2_rn(aa.z, aa.w);                      \
        ((uint2*)g_Y)[(row0 + rr) * 32 + tx] = cv.u;                  \
    }
    STORE_ROW(0, a0) STORE_ROW(1, a1) STORE_ROW(2, a2) STORE_ROW(3, a3)
#undef STORE_ROW
}

// ---------------- build kernel: hist -> scan -> fill, 512 thr, 3 blocks/SM ----------------
__global__ __launch_bounds__(BT, 3) void build_kernel(const int* __restrict__ hi1,
                                                      const int* __restrict__ hi2,
                                                      int nnz1, int nnz2) {
    const int T = G * BT;
    int gid = blockIdx.x * BT + threadIdx.x;
    int t = threadIdx.x, lane = t & 31, wid = t >> 5;

    // ---- Phase H: histogram + n2 run boundaries + tail ----
    if (nnz2 > 0) {
        int last = __ldg(&hi2[nnz2 - 1]);
        for (int k = gid; k < NN - last; k += T) g_n2ptr[last + 1 + k] = nnz2;
        for (int i = gid * 8; i < nnz2; i += T * 8) {
            int lim = (i + 8 <= nnz2) ? 8 : (nnz2 - i);
            int e[8], nd[8];
#pragma unroll
            for (int u = 0; u < 8; u++) {
                if (u < lim) {
                    e[u] = __ldg(&hi2[nnz2 + i + u]);
                    nd[u] = __ldg(&hi2[i + u]);
                }
            }
#pragma unroll
            for (int u = 0; u < 8; u++) {
                if (u < lim) atomicAdd(&g_ecnt[(NE + e[u]) * PAD], 1);
            }
            int pv = (i == 0) ? -1 : __ldg(&hi2[i - 1]);
#pragma unroll
            for (int u = 0; u < 8; u++) {
                if (u < lim) {
                    if (nd[u] != pv) {
                        for (int n = pv + 1; n <= nd[u]; n++) g_n2ptr[n] = i + u;
                    }
                    pv = nd[u];
                }
            }
        }
    }
    for (int k = gid; k < nnz1; k += T) {
        int node = __ldg(&hi1[k]), edge = __ldg(&hi1[nnz1 + k]);
        atomicAdd(&g_ecnt[edge * PAD], 1);
        atomicAdd(&g_n1cnt[node * PAD], 1);
    }

    grid_barrier(0);

    // ---- Phase S: scan (blocks 0..SC_T-1; others pass through) ----
    __shared__ int wsum[16];
    __shared__ int s_off;
    int b = blockIdx.x;
    bool scanner = (b < SC_T);
    int excl = 0, v = 0, i_sc = 0, n_sc = 0, lb = 0, nb = 0;
    int *ptr = 0, *pos = 0;

    if (scanner) {
        int *cnt, *bsum;
        if (b < SC_E) { cnt = g_ecnt; ptr = g_eptr; pos = g_epos; n_sc = 2 * NE; lb = b; nb = SC_E; bsum = g_bsumE; }
        else { cnt = g_n1cnt; ptr = g_n1ptr; pos = g_n1pos; n_sc = NN; lb = b - SC_E; nb = SC_N; bsum = g_bsumN; }
        i_sc = lb * BT + t;

        v = (i_sc < n_sc) ? cnt[i_sc * PAD] : 0;
        if (i_sc < n_sc) cnt[i_sc * PAD] = 0;  // re-zero (call-entry invariant)

        int inc = v;
#pragma unroll
        for (int o = 1; o < 32; o <<= 1) {
            int u = __shfl_up_sync(~0u, inc, o);
            if (lane >= o) inc += u;
        }
        if (lane == 31) wsum[wid] = inc;
        __syncthreads();
        if (wid == 0 && lane < 16) {
            int w = wsum[lane];
            int wi = w;
#pragma unroll
            for (int o = 1; o < 16; o <<= 1) {
                int u = __shfl_up_sync(0xffffu, wi, o);
                if (lane >= o) wi += u;
            }
            wsum[lane] = wi - w;
        }
        __syncthreads();
        excl = wsum[wid] + inc - v;
        if (t == BT - 1) bsum[lb] = excl + v;
    }

    grid_barrier(1);

    if (scanner) {
        const int* bsum = (b < SC_E) ? g_bsumE : g_bsumN;
        if (wid == 0) {
            int acc = 0;
            for (int q = lane; q < lb; q += 32) acc += bsum[q];
#pragma unroll
            for (int o = 16; o > 0; o >>= 1) acc += __shfl_down_sync(~0u, acc, o);
            if (lane == 0) s_off = acc;
        }
        __syncthreads();
        int off = s_off;
        if (i_sc < n_sc) { ptr[i_sc] = excl + off; pos[i_sc * PAD] = excl + off; }
        if (lb == nb - 1 && t == BT - 1) ptr[n_sc] = off + excl + v;
    }

    grid_barrier(2);

    // ---- Phase F: fill CSR ----
    for (int i = gid * 8; i < nnz2; i += T * 8) {
        int lim = (i + 8 <= nnz2) ? 8 : (nnz2 - i);
        if (lim == 8) {
            int nd[8], e[8], p[8];
#pragma unroll
            for (int u = 0; u < 8; u++) {
                nd[u] = __ldg(&hi2[i + u]);
                e[u] = __ldg(&hi2[nnz2 + i + u]);
            }
#pragma unroll
            for (int u = 0; u < 8; u++) p[u] = atomicAdd(&g_epos[(NE + e[u]) * PAD], 1);
#pragma unroll
            for (int u = 0; u < 8; u++) g_emem[p[u]] = nd[u];
        } else {
            for (int u = i; u < nnz2; u++) {
                int n0 = __ldg(&hi2[u]), e0 = __ldg(&hi2[nnz2 + u]);
                int p = atomicAdd(&g_epos[(NE + e0) * PAD], 1);
                g_emem[p] = n0;
            }
        }
    }
    for (int k = gid; k < nnz1; k += T) {
        int node = __ldg(&hi1[k]), edge = __ldg(&hi1[nnz1 + k]);
        int p = atomicAdd(&g_epos[edge * PAD], 1);
        int q = atomicAdd(&g_n1pos[node * PAD], 1);
        g_emem[p] = node;
        g_nmem1[q] = edge;
    }
}

// ---------------- gather kernel: edge_mean -> barrier -> node_out, 512 thr, 3/SM ---------
__global__ __launch_bounds__(BT, 3) void gather_kernel(const int* __restrict__ hi2, int nnz2,
                                                       const float* __restrict__ bout,
                                                       float* __restrict__ out) {
    int lane = threadIdx.x & 31;
    int wg = (blockIdx.x * BT + threadIdx.x) >> 5;
    const int NW = G * (BT / 32);  // 7104 warps

    // ---- Phase E: per-edge-slot mean ----
    const __half2* Y2 = (const __half2*)g_Y;
    for (int w = wg; w < 2 * NE; w += NW) {
        int beg = g_eptr[w], end = g_eptr[w + 1];
        int col = ((w >= NE) ? 32 : 0) + lane;
        float sx = 0.f, sy = 0.f;
        int j = beg;
        for (; j + 8 <= end; j += 8) {
            float2 f[8];
#pragma unroll
            for (int u = 0; u < 8; u++) {
                int n0 = g_emem[j + u];
                f[u] = __half22float2(Y2[n0 * 64 + col]);
            }
#pragma unroll
            for (int u = 0; u < 8; u++) { sx += f[u].x; sy += f[u].y; }
        }
        for (; j < end; j++) {
            int n0 = g_emem[j];
            float2 a = __half22float2(Y2[n0 * 64 + col]);
            sx += a.x;
            sy += a.y;
        }
        int cnt = end - beg;
        float inv = 1.f / (float)(cnt > 0 ? cnt : 1);
        ((__half2*)g_emean)[w * 32 + lane] = __floats2half2_rn(sx * inv, sy * inv);
    }

    grid_barrier(3);

    // ---- Phase N: per-node output ----
    const __half2* E2 = (const __half2*)g_emean;
    const int* hi2e = hi2 + nnz2;
    for (int w = wg; w < NN; w += NW) {
        float sx = 0.f, sy = 0.f;
        {
            int beg = g_n1ptr[w], end = g_n1ptr[w + 1];
            int j = beg;
            for (; j + 4 <= end; j += 4) {
                float2 f[4];
#pragma unroll
                for (int u = 0; u < 4; u++) {
                    int e = g_nmem1[j + u];
                    f[u] = __half22float2(E2[e * 32 + lane]);
                }
#pragma unroll
                for (int u = 0; u < 4; u++) { sx += f[u].x; sy += f[u].y; }
            }
            for (; j < end; j++) {
                int e = g_nmem1[j];
                float2 a = __half22float2(E2[e * 32 + lane]);
                sx += a.x;
                sy += a.y;
            }
        }
        {
            int beg = g_n2ptr[w], end = g_n2ptr[w + 1];
            int j = beg;
            for (; j + 8 <= end; j += 8) {
                float2 f[8];
#pragma unroll
                for (int u = 0; u < 8; u++) {
                    int e = __ldg(&hi2e[j + u]);
                    f[u] = __half22float2(E2[(NE + e) * 32 + lane]);
                }
#pragma unroll
                for (int u = 0; u < 8; u++) { sx += f[u].x; sy += f[u].y; }
            }
            for (; j < end; j++) {
                int e = __ldg(&hi2e[j]);
                float2 a = __half22float2(E2[(NE + e) * 32 + lane]);
                sx += a.x;
                sy += a.y;
            }
        }
        float2 bo = ((const float2*)bout)[lane];
        ((float2*)out)[w * 32 + lane] = make_float2(bo.x + 0.5f * sx, bo.y + 0.5f * sy);
    }
}

// ---------------- launcher: forked-stream DAG, 2 kernels on critical path ----------------
extern "C" void kernel_launch(void* const* d_in, const int* in_sizes, int n_in,
                              void* d_out, int out_size) {
    const float* x = (const float*)d_in[0];
    const int* hi1 = (const int*)d_in[1];
    const int* hi2 = (const int*)d_in[2];
    const float* W1 = (const float*)d_in[3];
    const float* b1 = (const float*)d_in[4];
    const float* W2 = (const float*)d_in[5];
    const float* b2 = (const float*)d_in[6];
    const float* Wout = (const float*)d_in[7];
    const float* bout = (const float*)d_in[8];
    float* out = (float*)d_out;

    int nnz1 = in_sizes[1] / 2;
    int nnz2 = in_sizes[2] / 2;

    // Fork: side branch computes fold -> gemm
    cudaEventRecord(hx.ev_fork, 0);
    cudaStreamWaitEvent(hx.side, hx.ev_fork, 0);
    fold_kernel<<<65, 256, 0, hx.side>>>(W1, b1, W2, b2, Wout);
    gemm_kernel<<<GEMM_BLOCKS, 256, 0, hx.side>>>(x);
    cudaEventRecord(hx.ev_gemm, hx.side);

    // Main branch: CSR build (hist+scan+fill fused via grid barriers)
    build_kernel<<<G, BT>>>(hi1, hi2, nnz1, nnz2);

    // Join, then fused gather (edge_mean + node_out)
    cudaStreamWaitEvent(0, hx.ev_gemm, 0);
    gather_kernel<<<G, BT>>>(hi2, nnz2, bout, out);
}

// round 14
// speedup vs baseline: 1.1294x; 1.0644x over previous
#include <cuda_runtime.h>
#include <cuda_fp16.h>

#define NN 10000
#define NE 4000
#define MAXM (4 * 1024 * 1024)
#define PAD 64      // 256B stride between atomic counters -> spreads across all LTS slices
#define G 444       // persistent grid: 3 blocks/SM x 148 SMs (launch_bounds(512,3))
#define BT 512

// scan chunk layout: 512 counters per chunk
#define SC_E 16     // ceil(2*NE / 512)
#define SC_N 20     // ceil(NN / 512)
#define SC_T (SC_E + SC_N)

// ---------------- device scratch (zero-initialized at module load) ----------------
__device__ float g_VT[128 * 128];
__device__ float g_cc[128];
__device__ __half g_Y[NN * 128];
__device__ __half g_emean[2 * NE * 64];
__device__ int g_ecnt[2 * NE * PAD];   // zeroed by scan after reading (invariant)
__device__ int g_epos[2 * NE * PAD];
__device__ int g_eptr[2 * NE + 1];
__device__ int g_n1cnt[NN * PAD];      // zeroed by scan after reading (invariant)
__device__ int g_n1pos[NN * PAD];
__device__ int g_n1ptr[NN + 1];
__device__ int g_n2ptr[NN + 1];        // fully rewritten each call
__device__ int g_emem[MAXM];
__device__ int g_nmem1[MAXM];
__device__ int g_bsumE[SC_E];          // overwritten before read each call
__device__ int g_bsumN[SC_N];
__device__ volatile int g_bar[4];      // per-site monotonic ticket counters

// grid-wide barrier: per-site counter; volatile-load polling
__device__ __forceinline__ void grid_barrier(int idx) {
    __syncthreads();
    if (threadIdx.x == 0) {
        __threadfence();
        int ticket = atomicAdd((int*)&g_bar[idx], 1);
        int target = ticket - (ticket % G) + G;
        while (g_bar[idx] < target) {}
        __threadfence();
    }
    __syncthreads();
}

// ---------------- side-stream plumbing ----------------
struct HxPlumbing {
    cudaStream_t side;
    cudaEvent_t ev_fork, ev_gemm;
    HxPlumbing() {
        cudaStreamCreateWithFlags(&side, cudaStreamNonBlocking);
        cudaEventCreateWithFlags(&ev_fork, cudaEventDisableTiming);
        cudaEventCreateWithFlags(&ev_gemm, cudaEventDisableTiming);
    }
};
static HxPlumbing hx;

// ---------------- fold weights (side stream) ----------------
__global__ void fold_kernel(const float* __restrict__ W1, const float* __restrict__ b1,
                            const float* __restrict__ W2, const float* __restrict__ b2,
                            const float* __restrict__ Wout) {
    int bb = blockIdx.x;
    if (bb < 64) {
        int idx = bb * 256 + threadIdx.x;
        int j = idx >> 7, k = idx & 127;
        int s = j >> 6, jo = j & 63;
        const float* W = s ? W2 : W1;
        float sum = 0.f;
#pragma unroll 8
        for (int h = 0; h < 128; h++) sum = fmaf(Wout[jo * 128 + h], W[h * 128 + k], sum);
        g_VT[k * 128 + j] = sum;
    } else {
        int j = threadIdx.x;
        if (j < 128) {
            int s = j >> 6, jo = j & 63;
            const float* b = s ? b2 : b1;
            float sum = 0.f;
#pragma unroll 8
            for (int h = 0; h < 128; h++) sum = fmaf(Wout[jo * 128 + h], b[h], sum);
            g_cc[j] = sum;
        }
    }
}

// ---------------- GEMM (side stream): Y = x @ Vcat^T + cc, fp16 out ----------------
#define GEMM_BLOCKS ((NN + 31) / 32)  // 313

#define FMA4(a, sc, v)                 \
    a.x = fmaf(sc, v.x, a.x);          \
    a.y = fmaf(sc, v.y, a.y);          \
    a.z = fmaf(sc, v.z, a.z);          \
    a.w = fmaf(sc, v.w, a.w);

__global__ __launch_bounds__(256) void gemm_kernel(const float* __restrict__ x) {
    int tx = threadIdx.x & 31;
    int ty = threadIdx.x >> 5;
    int row0 = blockIdx.x * 32 + ty * 4;
    const float4* x4 = (const float4*)x;
    const float4* v4 = (const float4*)g_VT;

    int rb0 = (row0 + 0 < NN ? row0 + 0 : NN - 1) * 32;
    int rb1 = (row0 + 1 < NN ? row0 + 1 : NN - 1) * 32;
    int rb2 = (row0 + 2 < NN ? row0 + 2 : NN - 1) * 32;
    int rb3 = (row0 + 3 < NN ? row0 + 3 : NN - 1) * 32;

    float4 a0 = make_float4(0.f, 0.f, 0.f, 0.f), a1 = a0, a2 = a0, a3 = a0;

#pragma unroll 4
    for (int k4 = 0; k4 < 32; k4++) {
        float4 v0 = v4[(4 * k4 + 0) * 32 + tx];
        float4 v1 = v4[(4 * k4 + 1) * 32 + tx];
        float4 v2 = v4[(4 * k4 + 2) * 32 + tx];
        float4 v3 = v4[(4 * k4 + 3) * 32 + tx];
        float4 q;
        q = x4[rb0 + k4];
        FMA4(a0, q.x, v0); FMA4(a0, q.y, v1); FMA4(a0, q.z, v2); FMA4(a0, q.w, v3);
        q = x4[rb1 + k4];
        FMA4(a1, q.x, v0); FMA4(a1, q.y, v1); FMA4(a1, q.z, v2); FMA4(a1, q.w, v3);
        q = x4[rb2 + k4];
        FMA4(a2, q.x, v0); FMA4(a2, q.y, v1); FMA4(a2, q.z, v2); FMA4(a2, q.w, v3);
        q = x4[rb3 + k4];
        FMA4(a3, q.x, v0); FMA4(a3, q.y, v1); FMA4(a3, q.z, v2); FMA4(a3, q.w, v3);
    }
    float4 c = ((const float4*)g_cc)[tx];
    a0.x += c.x; a0.y += c.y; a0.z += c.z; a0.w += c.w;
    a1.x += c.x; a1.y += c.y; a1.z += c.z; a1.w += c.w;
    a2.x += c.x; a2.y += c.y; a2.z += c.z; a2.w += c.w;
    a3.x += c.x; a3.y += c.y; a3.z += c.z; a3.w += c.w;

    union { __half2 h[2]; uint2 u; } cv;
#define STORE_ROW(rr, aa)                                             \
    if (row0 + rr < NN) {                                             \
        cv.h[0] = __floats2half2_rn(aa.x, aa.y);                      \
        cv.h[1] = __floats2half2_rn(aa.z, aa.w);                      \
        ((uint2*)g_Y)[(row0 + rr) * 32 + tx] = cv.u;                  \
    }
    STORE_ROW(0, a0) STORE_ROW(1, a1) STORE_ROW(2, a2) STORE_ROW(3, a3)
#undef STORE_ROW
}

// ---------------- build kernel: hist -> scan -> fill (persistent, proven in R13) ---------
__global__ __launch_bounds__(BT, 3) void build_kernel(const int* __restrict__ hi1,
                                                      const int* __restrict__ hi2,
                                                      int nnz1, int nnz2) {
    const int T = G * BT;
    int gid = blockIdx.x * BT + threadIdx.x;
    int t = threadIdx.x, lane = t & 31, wid = t >> 5;

    // ---- Phase H: histogram + n2 run boundaries + tail ----
    if (nnz2 > 0) {
        int last = __ldg(&hi2[nnz2 - 1]);
        for (int k = gid; k < NN - last; k += T) g_n2ptr[last + 1 + k] = nnz2;
        for (int i = gid * 8; i < nnz2; i += T * 8) {
            int lim = (i + 8 <= nnz2) ? 8 : (nnz2 - i);
            int e[8], nd[8];
#pragma unroll
            for (int u = 0; u < 8; u++) {
                if (u < lim) {
                    e[u] = __ldg(&hi2[nnz2 + i + u]);
                    nd[u] = __ldg(&hi2[i + u]);
                }
            }
#pragma unroll
            for (int u = 0; u < 8; u++) {
                if (u < lim) atomicAdd(&g_ecnt[(NE + e[u]) * PAD], 1);
            }
            int pv = (i == 0) ? -1 : __ldg(&hi2[i - 1]);
#pragma unroll
            for (int u = 0; u < 8; u++) {
                if (u < lim) {
                    if (nd[u] != pv) {
                        for (int n = pv + 1; n <= nd[u]; n++) g_n2ptr[n] = i + u;
                    }
                    pv = nd[u];
                }
            }
        }
    }
    for (int k = gid; k < nnz1; k += T) {
        int node = __ldg(&hi1[k]), edge = __ldg(&hi1[nnz1 + k]);
        atomicAdd(&g_ecnt[edge * PAD], 1);
        atomicAdd(&g_n1cnt[node * PAD], 1);
    }

    grid_barrier(0);

    // ---- Phase S: scan (blocks 0..SC_T-1; others pass through) ----
    __shared__ int wsum[16];
    __shared__ int s_off;
    int b = blockIdx.x;
    bool scanner = (b < SC_T);
    int excl = 0, v = 0, i_sc = 0, n_sc = 0, lb = 0, nb = 0;
    int *ptr = 0, *pos = 0;

    if (scanner) {
        int *cnt, *bsum;
        if (b < SC_E) { cnt = g_ecnt; ptr = g_eptr; pos = g_epos; n_sc = 2 * NE; lb = b; nb = SC_E; bsum = g_bsumE; }
        else { cnt = g_n1cnt; ptr = g_n1ptr; pos = g_n1pos; n_sc = NN; lb = b - SC_E; nb = SC_N; bsum = g_bsumN; }
        i_sc = lb * BT + t;

        v = (i_sc < n_sc) ? cnt[i_sc * PAD] : 0;
        if (i_sc < n_sc) cnt[i_sc * PAD] = 0;  // re-zero (call-entry invariant)

        int inc = v;
#pragma unroll
        for (int o = 1; o < 32; o <<= 1) {
            int u = __shfl_up_sync(~0u, inc, o);
            if (lane >= o) inc += u;
        }
        if (lane == 31) wsum[wid] = inc;
        __syncthreads();
        if (wid == 0 && lane < 16) {
            int w = wsum[lane];
            int wi = w;
#pragma unroll
            for (int o = 1; o < 16; o <<= 1) {
                int u = __shfl_up_sync(0xffffu, wi, o);
                if (lane >= o) wi += u;
            }
            wsum[lane] = wi - w;
        }
        __syncthreads();
        excl = wsum[wid] + inc - v;
        if (t == BT - 1) bsum[lb] = excl + v;
    }

    grid_barrier(1);

    if (scanner) {
        const int* bsum = (b < SC_E) ? g_bsumE : g_bsumN;
        if (wid == 0) {
            int acc = 0;
            for (int q = lane; q < lb; q += 32) acc += bsum[q];
#pragma unroll
            for (int o = 16; o > 0; o >>= 1) acc += __shfl_down_sync(~0u, acc, o);
            if (lane == 0) s_off = acc;
        }
        __syncthreads();
        int off = s_off;
        if (i_sc < n_sc) { ptr[i_sc] = excl + off; pos[i_sc * PAD] = excl + off; }
        if (lb == nb - 1 && t == BT - 1) ptr[n_sc] = off + excl + v;
    }

    grid_barrier(2);

    // ---- Phase F: fill CSR ----
    for (int i = gid * 8; i < nnz2; i += T * 8) {
        int lim = (i + 8 <= nnz2) ? 8 : (nnz2 - i);
        if (lim == 8) {
            int nd[8], e[8], p[8];
#pragma unroll
            for (int u = 0; u < 8; u++) {
                nd[u] = __ldg(&hi2[i + u]);
                e[u] = __ldg(&hi2[nnz2 + i + u]);
            }
#pragma unroll
            for (int u = 0; u < 8; u++) p[u] = atomicAdd(&g_epos[(NE + e[u]) * PAD], 1);
#pragma unroll
            for (int u = 0; u < 8; u++) g_emem[p[u]] = nd[u];
        } else {
            for (int u = i; u < nnz2; u++) {
                int n0 = __ldg(&hi2[u]), e0 = __ldg(&hi2[nnz2 + u]);
                int p = atomicAdd(&g_epos[(NE + e0) * PAD], 1);
                g_emem[p] = n0;
            }
        }
    }
    for (int k = gid; k < nnz1; k += T) {
        int node = __ldg(&hi1[k]), edge = __ldg(&hi1[nnz1 + k]);
        int p = atomicAdd(&g_epos[edge * PAD], 1);
        int q = atomicAdd(&g_n1pos[node * PAD], 1);
        g_emem[p] = node;
        g_nmem1[q] = edge;
    }
}

// ---------------- per-edge-slot mean (warp per slot, full occupancy) ----------------
__global__ void edge_mean_kernel() {
    int w = (blockIdx.x * 256 + threadIdx.x) >> 5;
    int lane = threadIdx.x & 31;
    if (w >= 2 * NE) return;
    int beg = g_eptr[w], end = g_eptr[w + 1];
    int col = ((w >= NE) ? 32 : 0) + lane;
    const __half2* Y2 = (const __half2*)g_Y;
    float sx = 0.f, sy = 0.f;
    int j = beg;
    for (; j + 8 <= end; j += 8) {
        float2 f[8];
#pragma unroll
        for (int u = 0; u < 8; u++) {
            int n0 = g_emem[j + u];
            f[u] = __half22float2(Y2[n0 * 64 + col]);
        }
#pragma unroll
        for (int u = 0; u < 8; u++) { sx += f[u].x; sy += f[u].y; }
    }
    for (; j < end; j++) {
        int n0 = g_emem[j];
        float2 a = __half22float2(Y2[n0 * 64 + col]);
        sx += a.x;
        sy += a.y;
    }
    int cnt = end - beg;
    float inv = 1.f / (float)(cnt > 0 ? cnt : 1);
    ((__half2*)g_emean)[w * 32 + lane] = __floats2half2_rn(sx * inv, sy * inv);
}

// ---------------- per-node output (warp per node, full occupancy) ----------------
__global__ void node_out_kernel(const int* __restrict__ hi2, int nnz2,
                                const float* __restrict__ bout, float* __restrict__ out) {
    int w = (blockIdx.x * 256 + threadIdx.x) >> 5;
    int lane = threadIdx.x & 31;
    if (w >= NN) return;
    const __half2* E2 = (const __half2*)g_emean;
    const int* hi2e = hi2 + nnz2;
    float sx = 0.f, sy = 0.f;

    {
        int beg = g_n1ptr[w], end = g_n1ptr[w + 1];
        int j = beg;
        for (; j + 4 <= end; j += 4) {
            float2 f[4];
#pragma unroll
            for (int u = 0; u < 4; u++) {
                int e = g_nmem1[j + u];
                f[u] = __half22float2(E2[e * 32 + lane]);
            }
#pragma unroll
            for (int u = 0; u < 4; u++) { sx += f[u].x; sy += f[u].y; }
        }
        for (; j < end; j++) {
            int e = g_nmem1[j];
            float2 a = __half22float2(E2[e * 32 + lane]);
            sx += a.x;
            sy += a.y;
        }
    }
    {
        int beg = g_n2ptr[w], end = g_n2ptr[w + 1];
        int j = beg;
        for (; j + 8 <= end; j += 8) {
            float2 f[8];
#pragma unroll
            for (int u = 0; u < 8; u++) {
                int e = __ldg(&hi2e[j + u]);
                f[u] = __half22float2(E2[(NE + e) * 32 + lane]);
            }
#pragma unroll
            for (int u = 0; u < 8; u++) { sx += f[u].x; sy += f[u].y; }
        }
        for (; j < end; j++) {
            int e = __ldg(&hi2e[j]);
            float2 a = __half22float2(E2[(NE + e) * 32 + lane]);
            sx += a.x;
            sy += a.y;
        }
    }
    float2 bo = ((const float2*)bout)[lane];
    ((float2*)out)[w * 32 + lane] = make_float2(bo.x + 0.5f * sx, bo.y + 0.5f * sy);
}

// ---------------- launcher: forked-stream DAG ----------------
extern "C" void kernel_launch(void* const* d_in, const int* in_sizes, int n_in,
                              void* d_out, int out_size) {
    const float* x = (const float*)d_in[0];
    const int* hi1 = (const int*)d_in[1];
    const int* hi2 = (const int*)d_in[2];
    const float* W1 = (const float*)d_in[3];
    const float* b1 = (const float*)d_in[4];
    const float* W2 = (const float*)d_in[5];
    const float* b2 = (const float*)d_in[6];
    const float* Wout = (const float*)d_in[7];
    const float* bout = (const float*)d_in[8];
    float* out = (float*)d_out;

    int nnz1 = in_sizes[1] / 2;
    int nnz2 = in_sizes[2] / 2;

    // Fork: side branch computes fold -> gemm
    cudaEventRecord(hx.ev_fork, 0);
    cudaStreamWaitEvent(hx.side, hx.ev_fork, 0);
    fold_kernel<<<65, 256, 0, hx.side>>>(W1, b1, W2, b2, Wout);
    gemm_kernel<<<GEMM_BLOCKS, 256, 0, hx.side>>>(x);
    cudaEventRecord(hx.ev_gemm, hx.side);

    // Main branch: CSR build (hist+scan+fill fused via grid barriers — proven R13)
    build_kernel<<<G, BT>>>(hi1, hi2, nnz1, nnz2);

    // Join, then separate full-occupancy gather launches (champion config)
    cudaStreamWaitEvent(0, hx.ev_gemm, 0);
    edge_mean_kernel<<<(2 * NE * 32 + 255) / 256, 256>>>();
    node_out_kernel<<<(NN * 32 + 255) / 256, 256>>>(hi2, nnz2, bout, out);
}

// round 15
// speedup vs baseline: 1.3102x; 1.1601x over previous
#include <cuda_runtime.h>
#include <cuda_fp16.h>

#define NN 10000
#define NE 4000
#define MAXM (4 * 1024 * 1024)
#define PAD 64  // 256B stride between atomic counters -> spreads across all LTS slices

// scan layout: 512 counters per block
#define EBLKS 16   // ceil(2*NE / 512)
#define NBLKS 20   // ceil(NN / 512)

// ---------------- device scratch (zero-initialized at module load) ----------------
__device__ float g_VT[128 * 128];
__device__ float g_cc[128];
__device__ __half g_Y[NN * 128];
__device__ __half g_emean[2 * NE * 64];
__device__ int g_ecnt[2 * NE * PAD];   // zeroed by scan1 after reading (invariant)
__device__ int g_epos[2 * NE * PAD];
__device__ int g_eptr[2 * NE + 1];
__device__ int g_n1cnt[NN * PAD];      // zeroed by scan1 after reading (invariant)
__device__ int g_n1pos[NN * PAD];
__device__ int g_n1ptr[NN + 1];
__device__ int g_n2ptr[NN + 1];        // fully rewritten by hist each call
__device__ int g_emem[MAXM];
__device__ int g_nmem1[MAXM];
__device__ int g_bsumE[EBLKS];         // overwritten before read each call
__device__ int g_bsumN[NBLKS];

// ---------------- side-stream plumbing ----------------
struct HxPlumbing {
    cudaStream_t side;
    cudaEvent_t ev_fork, ev_gemm;
    HxPlumbing() {
        cudaStreamCreateWithFlags(&side, cudaStreamNonBlocking);
        cudaEventCreateWithFlags(&ev_fork, cudaEventDisableTiming);
        cudaEventCreateWithFlags(&ev_gemm, cudaEventDisableTiming);
    }
};
static HxPlumbing hx;

// ---------------- fold weights (side stream) ----------------
__global__ void fold_kernel(const float* __restrict__ W1, const float* __restrict__ b1,
                            const float* __restrict__ W2, const float* __restrict__ b2,
                            const float* __restrict__ Wout) {
    int bb = blockIdx.x;
    if (bb < 64) {
        int idx = bb * 256 + threadIdx.x;
        int j = idx >> 7, k = idx & 127;
        int s = j >> 6, jo = j & 63;
        const float* W = s ? W2 : W1;
        float sum = 0.f;
#pragma unroll 8
        for (int h = 0; h < 128; h++) sum = fmaf(Wout[jo * 128 + h], W[h * 128 + k], sum);
        g_VT[k * 128 + j] = sum;
    } else {
        int j = threadIdx.x;
        if (j < 128) {
            int s = j >> 6, jo = j & 63;
            const float* b = s ? b2 : b1;
            float sum = 0.f;
#pragma unroll 8
            for (int h = 0; h < 128; h++) sum = fmaf(Wout[jo * 128 + h], b[h], sum);
            g_cc[j] = sum;
        }
    }
}

// ---------------- GEMM (side stream): Y = x @ Vcat^T + cc, fp16 out ----------------
#define GEMM_BLOCKS ((NN + 31) / 32)  // 313

#define FMA4(a, sc, v)                 \
    a.x = fmaf(sc, v.x, a.x);          \
    a.y = fmaf(sc, v.y, a.y);          \
    a.z = fmaf(sc, v.z, a.z);          \
    a.w = fmaf(sc, v.w, a.w);

__global__ __launch_bounds__(256) void gemm_kernel(const float* __restrict__ x) {
    int tx = threadIdx.x & 31;
    int ty = threadIdx.x >> 5;
    int row0 = blockIdx.x * 32 + ty * 4;
    const float4* x4 = (const float4*)x;
    const float4* v4 = (const float4*)g_VT;

    int rb0 = (row0 + 0 < NN ? row0 + 0 : NN - 1) * 32;
    int rb1 = (row0 + 1 < NN ? row0 + 1 : NN - 1) * 32;
    int rb2 = (row0 + 2 < NN ? row0 + 2 : NN - 1) * 32;
    int rb3 = (row0 + 3 < NN ? row0 + 3 : NN - 1) * 32;

    float4 a0 = make_float4(0.f, 0.f, 0.f, 0.f), a1 = a0, a2 = a0, a3 = a0;

#pragma unroll 4
    for (int k4 = 0; k4 < 32; k4++) {
        float4 v0 = v4[(4 * k4 + 0) * 32 + tx];
        float4 v1 = v4[(4 * k4 + 1) * 32 + tx];
        float4 v2 = v4[(4 * k4 + 2) * 32 + tx];
        float4 v3 = v4[(4 * k4 + 3) * 32 + tx];
        float4 q;
        q = x4[rb0 + k4];
        FMA4(a0, q.x, v0); FMA4(a0, q.y, v1); FMA4(a0, q.z, v2); FMA4(a0, q.w, v3);
        q = x4[rb1 + k4];
        FMA4(a1, q.x, v0); FMA4(a1, q.y, v1); FMA4(a1, q.z, v2); FMA4(a1, q.w, v3);
        q = x4[rb2 + k4];
        FMA4(a2, q.x, v0); FMA4(a2, q.y, v1); FMA4(a2, q.z, v2); FMA4(a2, q.w, v3);
        q = x4[rb3 + k4];
        FMA4(a3, q.x, v0); FMA4(a3, q.y, v1); FMA4(a3, q.z, v2); FMA4(a3, q.w, v3);
    }
    float4 c = ((const float4*)g_cc)[tx];
    a0.x += c.x; a0.y += c.y; a0.z += c.z; a0.w += c.w;
    a1.x += c.x; a1.y += c.y; a1.z += c.z; a1.w += c.w;
    a2.x += c.x; a2.y += c.y; a2.z += c.z; a2.w += c.w;
    a3.x += c.x; a3.y += c.y; a3.z += c.z; a3.w += c.w;

    union { __half2 h[2]; uint2 u; } cv;
#define STORE_ROW(rr, aa)                                             \
    if (row0 + rr < NN) {                                             \
        cv.h[0] = __floats2half2_rn(aa.x, aa.y);                      \
        cv.h[1] = __floats2half2_rn(aa.z, aa.w);                      \
        ((uint2*)g_Y)[(row0 + rr) * 32 + tx] = cv.u;                  \
    }
    STORE_ROW(0, a0) STORE_ROW(1, a1) STORE_ROW(2, a2) STORE_ROW(3, a3)
#undef STORE_ROW
}

// ---------------- histogram (8/thread) + n2 run boundaries + n2 tail fill ----------------
__global__ __launch_bounds__(256) void hist_kernel(const int* __restrict__ hi1,
                                                   const int* __restrict__ hi2,
                                                   int nnz1, int nnz2, int B2h) {
    if (blockIdx.x < B2h) {
        int gid = blockIdx.x * 256 + threadIdx.x;

        int last = __ldg(&hi2[nnz2 - 1]);
        if (gid < NN - last) g_n2ptr[last + 1 + gid] = nnz2;

        int i = gid * 8;
        if (i >= nnz2) return;
        int lim = (i + 8 <= nnz2) ? 8 : (nnz2 - i);
        int e[8], nd[8];
#pragma unroll
        for (int u = 0; u < 8; u++) {
            if (u < lim) {
                e[u] = __ldg(&hi2[nnz2 + i + u]);
                nd[u] = __ldg(&hi2[i + u]);
            }
        }
#pragma unroll
        for (int u = 0; u < 8; u++) {
            if (u < lim) atomicAdd(&g_ecnt[(NE + e[u]) * PAD], 1);
        }
        int pv = (i == 0) ? -1 : __ldg(&hi2[i - 1]);
#pragma unroll
        for (int u = 0; u < 8; u++) {
            if (u < lim) {
                if (nd[u] != pv) {
                    for (int n = pv + 1; n <= nd[u]; n++) g_n2ptr[n] = i + u;
                }
                pv = nd[u];
            }
        }
    } else {
        int k = (blockIdx.x - B2h) * 256 + threadIdx.x;
        if (k >= nnz1) return;
        int node = __ldg(&hi1[k]), edge = __ldg(&hi1[nnz1 + k]);
        atomicAdd(&g_ecnt[edge * PAD], 1);
        atomicAdd(&g_n1cnt[node * PAD], 1);
    }
}

// ---------------- scan phase 1: per-block local scan + totals (36 blocks) ----------------
__global__ __launch_bounds__(512) void scan1_kernel() {
    __shared__ int wsum[16];
    int b = blockIdx.x;
    int *cnt, *ptr, *pos, *bsum;
    int n, base;
    if (b < EBLKS) { cnt = g_ecnt; ptr = g_eptr; pos = g_epos; n = 2 * NE; base = b * 512; bsum = &g_bsumE[b]; }
    else { cnt = g_n1cnt; ptr = g_n1ptr; pos = g_n1pos; n = NN; base = (b - EBLKS) * 512; bsum = &g_bsumN[b - EBLKS]; }

    int t = threadIdx.x, lane = t & 31, wid = t >> 5;
    int i = base + t;
    int v = (i < n) ? cnt[i * PAD] : 0;
    if (i < n) cnt[i * PAD] = 0;

    int inc = v;
#pragma unroll
    for (int o = 1; o < 32; o <<= 1) {
        int u = __shfl_up_sync(~0u, inc, o);
        if (lane >= o) inc += u;
    }
    if (lane == 31) wsum[wid] = inc;
    __syncthreads();
    if (wid == 0 && lane < 16) {
        int w = wsum[lane];
        int wi = w;
#pragma unroll
        for (int o = 1; o < 16; o <<= 1) {
            int u = __shfl_up_sync(0xffffu, wi, o);
            if (lane >= o) wi += u;
        }
        wsum[lane] = wi - w;
    }
    __syncthreads();
    int excl = wsum[wid] + inc - v;
    if (i < n) { ptr[i] = excl; pos[i * PAD] = excl; }
    if (t == 511) *bsum = excl + v;
}

// ---------------- scan phase 2: add block offsets (36 blocks) ----------------
__global__ __launch_bounds__(512) void scan2_kernel() {
    __shared__ int s_off;
    int b = blockIdx.x;
    int *ptr, *pos;
    const int* bs;
    int n, base, lb, nb;
    if (b < EBLKS) { ptr = g_eptr; pos = g_epos; n = 2 * NE; lb = b; nb = EBLKS; bs = g_bsumE; base = b * 512; }
    else { ptr = g_n1ptr; pos = g_n1pos; n = NN; lb = b - EBLKS; nb = NBLKS; bs = g_bsumN; base = lb * 512; }

    if (threadIdx.x < 32) {
        int lane = threadIdx.x;
        int vall = (lane < nb) ? bs[lane] : 0;
        int voff = (lane < lb) ? vall : 0;
        int off = __reduce_add_sync(0xffffffffu, voff);
        int full = __reduce_add_sync(0xffffffffu, vall);
        if (lane == 0) {
            s_off = off;
            if (lb == nb - 1) ptr[n] = full;
        }
    }
    __syncthreads();
    int off = s_off;
    int i = base + threadIdx.x;
    if (i < n) { ptr[i] += off; pos[i * PAD] += off; }
}

// ---------------- fill CSR (lean, batched 8/thread) ----------------
__global__ __launch_bounds__(256) void fill_kernel(const int* __restrict__ hi1,
                                                   const int* __restrict__ hi2,
                                                   int nnz1, int nnz2, int B2f) {
    if (blockIdx.x < B2f) {
        int i = (blockIdx.x * 256 + threadIdx.x) * 8;
        if (i >= nnz2) return;
        if (i + 8 <= nnz2) {
            int nd[8], e[8], p[8];
#pragma unroll
            for (int u = 0; u < 8; u++) {
                nd[u] = __ldg(&hi2[i + u]);
                e[u] = __ldg(&hi2[nnz2 + i + u]);
            }
#pragma unroll
            for (int u = 0; u < 8; u++) p[u] = atomicAdd(&g_epos[(NE + e[u]) * PAD], 1);
#pragma unroll
            for (int u = 0; u < 8; u++) g_emem[p[u]] = nd[u];
        } else {
            for (int u = i; u < nnz2; u++) {
                int n0 = __ldg(&hi2[u]), e0 = __ldg(&hi2[nnz2 + u]);
                int p = atomicAdd(&g_epos[(NE + e0) * PAD], 1);
                g_emem[p] = n0;
            }
        }
    } else {
        int k = (blockIdx.x - B2f) * 256 + threadIdx.x;
        if (k >= nnz1) return;
        int node = __ldg(&hi1[k]), edge = __ldg(&hi1[nnz1 + k]);
        int p = atomicAdd(&g_epos[edge * PAD], 1);
        int q = atomicAdd(&g_n1pos[node * PAD], 1);
        g_emem[p] = node;
        g_nmem1[q] = edge;
    }
}

// ---------------- per-edge-slot mean: BLOCK per slot, 8-warp split + smem reduce ---------
__global__ __launch_bounds__(256) void edge_mean_kernel() {
    __shared__ float2 red[8][32];
    int w = blockIdx.x;                  // slot id (0..2*NE-1)
    int lane = threadIdx.x & 31, wid = threadIdx.x >> 5;
    int beg = g_eptr[w], end = g_eptr[w + 1];
    int col = ((w >= NE) ? 32 : 0) + lane;
    const __half2* Y2 = (const __half2*)g_Y;
    float sx = 0.f, sy = 0.f;
    int j = beg + wid;
    for (; j + 16 <= end; j += 16) {     // 2-deep unroll per warp (stride 8 warps)
        int n0 = g_emem[j];
        int n1 = g_emem[j + 8];
        float2 a = __half22float2(Y2[n0 * 64 + col]);
        float2 b = __half22float2(Y2[n1 * 64 + col]);
        sx += a.x + b.x;
        sy += a.y + b.y;
    }
    for (; j < end; j += 8) {
        int n0 = g_emem[j];
        float2 a = __half22float2(Y2[n0 * 64 + col]);
        sx += a.x;
        sy += a.y;
    }
    red[wid][lane] = make_float2(sx, sy);
    __syncthreads();
    if (wid == 0) {
        float2 acc = red[0][lane];
#pragma unroll
        for (int u = 1; u < 8; u++) { acc.x += red[u][lane].x; acc.y += red[u][lane].y; }
        int cnt = end - beg;
        float inv = 1.f / (float)(cnt > 0 ? cnt : 1);
        ((__half2*)g_emean)[w * 32 + lane] = __floats2half2_rn(acc.x * inv, acc.y * inv);
    }
}

// ---------------- per-node output: BLOCK per node, 8-warp split + smem reduce ------------
__global__ __launch_bounds__(256) void node_out_kernel(const int* __restrict__ hi2, int nnz2,
                                                       const float* __restrict__ bout,
                                                       float* __restrict__ out) {
    __shared__ float2 red[8][32];
    int w = blockIdx.x;                  // node id
    int lane = threadIdx.x & 31, wid = threadIdx.x >> 5;
    const __half2* E2 = (const __half2*)g_emean;
    const int* hi2e = hi2 + nnz2;
    float sx = 0.f, sy = 0.f;

    // scale-1 members (g_nmem1 CSR)
    {
        int beg = g_n1ptr[w], end = g_n1ptr[w + 1];
        for (int j = beg + wid; j < end; j += 8) {
            int e = g_nmem1[j];
            float2 a = __half22float2(E2[e * 32 + lane]);
            sx += a.x;
            sy += a.y;
        }
    }
    // scale-2 members: contiguous run in sorted hi2
    {
        int beg = g_n2ptr[w], end = g_n2ptr[w + 1];
        int j = beg + wid;
        for (; j + 16 <= end; j += 16) {
            int e0 = __ldg(&hi2e[j]);
            int e1 = __ldg(&hi2e[j + 8]);
            float2 a = __half22float2(E2[(NE + e0) * 32 + lane]);
            float2 b = __half22float2(E2[(NE + e1) * 32 + lane]);
            sx += a.x + b.x;
            sy += a.y + b.y;
        }
        for (; j < end; j += 8) {
            int e = __ldg(&hi2e[j]);
            float2 a = __half22float2(E2[(NE + e) * 32 + lane]);
            sx += a.x;
            sy += a.y;
        }
    }
    red[wid][lane] = make_float2(sx, sy);
    __syncthreads();
    if (wid == 0) {
        float2 acc = red[0][lane];
#pragma unroll
        for (int u = 1; u < 8; u++) { acc.x += red[u][lane].x; acc.y += red[u][lane].y; }
        float2 bo = ((const float2*)bout)[lane];
        ((float2*)out)[w * 32 + lane] = make_float2(bo.x + 0.5f * acc.x, bo.y + 0.5f * acc.y);
    }
}

// ---------------- launcher: forked-stream DAG (R10 champion skeleton) ----------------
extern "C" void kernel_launch(void* const* d_in, const int* in_sizes, int n_in,
                              void* d_out, int out_size) {
    const float* x = (const float*)d_in[0];
    const int* hi1 = (const int*)d_in[1];
    const int* hi2 = (const int*)d_in[2];
    const float* W1 = (const float*)d_in[3];
    const float* b1 = (const float*)d_in[4];
    const float* W2 = (const float*)d_in[5];
    const float* b2 = (const float*)d_in[6];
    const float* Wout = (const float*)d_in[7];
    const float* bout = (const float*)d_in[8];
    float* out = (float*)d_out;

    int nnz1 = in_sizes[1] / 2;
    int nnz2 = in_sizes[2] / 2;

    // Fork: side branch computes fold -> gemm
    cudaEventRecord(hx.ev_fork, 0);
    cudaStreamWaitEvent(hx.side, hx.ev_fork, 0);
    fold_kernel<<<65, 256, 0, hx.side>>>(W1, b1, W2, b2, Wout);
    gemm_kernel<<<GEMM_BLOCKS, 256, 0, hx.side>>>(x);
    cudaEventRecord(hx.ev_gemm, hx.side);

    // Main branch: CSR build (separate lean kernels — champion config)
    int B2h = (nnz2 + 2047) / 2048;
    hist_kernel<<<B2h + (nnz1 + 255) / 256, 256>>>(hi1, hi2, nnz1, nnz2, B2h);
    scan1_kernel<<<EBLKS + NBLKS, 512>>>();
    scan2_kernel<<<EBLKS + NBLKS, 512>>>();
    int B2f = (nnz2 + 2047) / 2048;
    fill_kernel<<<B2f + (nnz1 + 255) / 256, 256>>>(hi1, hi2, nnz1, nnz2, B2f);

    // Join: gather stages need both Y (side) and CSR (main)
    cudaStreamWaitEvent(0, hx.ev_gemm, 0);
    edge_mean_kernel<<<2 * NE, 256>>>();
    node_out_kernel<<<NN, 256>>>(hi2, nnz2, bout, out);
}